// round 16
// baseline (speedup 1.0000x reference)
#include <cuda_runtime.h>
#include <cuda_fp16.h>
#include <cstdint>

#define D 128
#define NN 50000
#define NE 500000
#define TILE 64                     // X-tile rows per CTA
#define NT 512                      // 16 warps: 4(M) x 4(N)
#define SSTR 136                    // stage row stride in floats (136%32==8)

#define BAR_GRP(id) asm volatile("bar.sync %0, 128;" :: "r"(id) : "memory")

// ---------------- scratch (__device__ globals) ------------------------------
__device__ float g_psrc[(size_t)NN * D];
__device__ float g_ptgt[(size_t)NN * D];
__device__ float g_agg [(size_t)NN * D];
__device__ unsigned char g_wimg[65536];       // W_e2e [hi 32KB | lo 32KB] swizzled

// ---------------- smem layout (~105KB -> 2 CTAs/SM) -------------------------
#define SM_XHI  0                   // 16KB (alive through epilogue: residual)
#define SM_XLO  16384               // 16KB
#define SM_WHI  32768               // 32KB (dead after mma)
#define SM_WLO  65536               // 32KB (dead after mma)
#define SM_GSTG 32768               // gather stage (aliases W-hi, post-mma only)
#define SM_OSTG 67584               // output stage (aliases W-lo tail, post-mma only)
#define SM_RED  102400              // float2 red[64][4] = 2KB
#define SM_IDX  104448              // int2 idx[64] = 512B
#define SM_TOTAL 104960

// swizzled fp16 tile: row r x col c; 256B/row, 16B chunks; chunk ^= (r&7)
__device__ __forceinline__ uint32_t xswz(int r, int c) {
    return (uint32_t)(r * 256 + (((c >> 3) ^ (r & 7)) << 4) + (c & 7) * 2);
}

#define LDSM4(r, a) \
    asm volatile("ldmatrix.sync.aligned.m8n8.x4.shared.b16 {%0,%1,%2,%3}, [%4];" \
        : "=r"((r)[0]), "=r"((r)[1]), "=r"((r)[2]), "=r"((r)[3]) : "r"(a))
#define MMA(c, a, b) \
    asm volatile("mma.sync.aligned.m16n8k16.row.col.f32.f16.f16.f32 " \
        "{%0,%1,%2,%3}, {%4,%5,%6,%7}, {%8,%9}, {%0,%1,%2,%3};" \
        : "+f"((c)[0]), "+f"((c)[1]), "+f"((c)[2]), "+f"((c)[3]) \
        : "r"((a)[0]), "r"((a)[1]), "r"((a)[2]), "r"((a)[3]), "r"((b)[0]), "r"((b)[1]))
#define CP16(dst, src) \
    asm volatile("cp.async.cg.shared.global [%0], [%1], 16;" :: "r"(dst), "l"(src))
#define CP_COMMIT() asm volatile("cp.async.commit_group;" ::: "memory")
#define CP_WAIT()   asm volatile("cp.async.wait_group 0;" ::: "memory")

__device__ __forceinline__ uint32_t smem_u32(const void* p) {
    uint32_t a;
    asm("{ .reg .u64 t; cvta.to.shared.u64 t, %1; cvt.u32.u64 %0, t; }" : "=r"(a) : "l"(p));
    return a;
}
__device__ __forceinline__ unsigned short h_us(__half h) { return __half_as_ushort(h); }
__device__ __forceinline__ float silu(float m) { return m * (1.f / (1.f + __expf(-m))); }

// convert fp32 tile [TILE x 128] -> split hi/lo fp16 in swizzled smem (stream loads)
__device__ __forceinline__ void convert_tile(const float* __restrict__ src, int row0,
                                             int nrows, char* a_hi, char* a_lo) {
    #pragma unroll
    for (int it = 0; it < 4; it++) {
        int i = threadIdx.x + it * NT;
        int r = i >> 5;
        int c = (i & 31) << 2;
        float4 v = make_float4(0.f, 0.f, 0.f, 0.f);
        if (row0 + r < nrows) v = __ldcs((const float4*)(src + (size_t)(row0 + r) * D + c));
        __half h0 = __float2half_rn(v.x), h1 = __float2half_rn(v.y);
        __half h2 = __float2half_rn(v.z), h3 = __float2half_rn(v.w);
        __half l0 = __float2half_rn(v.x - __half2float(h0));
        __half l1 = __float2half_rn(v.y - __half2float(h1));
        __half l2 = __float2half_rn(v.z - __half2float(h2));
        __half l3 = __float2half_rn(v.w - __half2float(h3));
        uint32_t off = xswz(r, c);
        *(uint2*)(a_hi + off) = make_uint2((uint32_t)h_us(h0) | ((uint32_t)h_us(h1) << 16),
                                           (uint32_t)h_us(h2) | ((uint32_t)h_us(h3) << 16));
        *(uint2*)(a_lo + off) = make_uint2((uint32_t)h_us(l0) | ((uint32_t)h_us(l1) << 16),
                                           (uint32_t)h_us(l2) | ((uint32_t)h_us(l3) << 16));
    }
}

// convert raw fp32 W [128 x 128] -> split hi/lo fp16 in swizzled smem
__device__ __forceinline__ void convert_w(const float* __restrict__ W,
                                          char* w_hi, char* w_lo) {
    #pragma unroll
    for (int it = 0; it < 8; it++) {
        int i = threadIdx.x + it * NT;       // 4096 float4 slots
        int r = i >> 5;
        int c = (i & 31) << 2;
        float4 v = *(const float4*)(W + (size_t)r * D + c);
        __half h0 = __float2half_rn(v.x), h1 = __float2half_rn(v.y);
        __half h2 = __float2half_rn(v.z), h3 = __float2half_rn(v.w);
        __half l0 = __float2half_rn(v.x - __half2float(h0));
        __half l1 = __float2half_rn(v.y - __half2float(h1));
        __half l2 = __float2half_rn(v.z - __half2float(h2));
        __half l3 = __float2half_rn(v.w - __half2float(h3));
        uint32_t off = xswz(r, c);
        *(uint2*)(w_hi + off) = make_uint2((uint32_t)h_us(h0) | ((uint32_t)h_us(h1) << 16),
                                           (uint32_t)h_us(h2) | ((uint32_t)h_us(h3) << 16));
        *(uint2*)(w_lo + off) = make_uint2((uint32_t)h_us(l0) | ((uint32_t)h_us(l1) << 16),
                                           (uint32_t)h_us(l2) | ((uint32_t)h_us(l3) << 16));
    }
}

__device__ __forceinline__ void copy_wimg_async(uint32_t sdst) {
    const char* src = (const char*)g_wimg;
    #pragma unroll 2
    for (int i = threadIdx.x; i < 4096; i += NT)
        CP16(sdst + i * 16, src + i * 16);
    CP_COMMIT();
}

// ---------------------------------------------------------------------------
// GEMM mainloop: 16 warps 4(M)x4(N); warp tile 16x32; acc[4][4] f32.
// 3-term split: HH + HL + LH.
// ---------------------------------------------------------------------------
__device__ __forceinline__ void mma_loop(uint32_t sXhi, uint32_t sXlo,
                                         uint32_t sWhi, uint32_t sWlo,
                                         float (&acc)[4][4], int mrow, int ncol, int lane) {
    int arow = mrow + (lane & 15);
    int g = lane >> 3;
    int brow = ncol + ((g >> 1) << 3) + (lane & 7);
    int bkc = g & 1;
    #pragma unroll
    for (int ks = 0; ks < 8; ks++) {
        int ac16 = ks * 2 + (lane >> 4);
        uint32_t aoff = (uint32_t)(arow * 256 + ((ac16 ^ (arow & 7)) << 4));
        uint32_t ah[4], al[4];
        LDSM4(ah, sXhi + aoff);
        LDSM4(al, sXlo + aoff);
        int bc16 = ks * 2 + bkc;
        #pragma unroll
        for (int np = 0; np < 2; np++) {
            int n = brow + np * 16;
            uint32_t boff = (uint32_t)(n * 256 + ((bc16 ^ (n & 7)) << 4));
            uint32_t bh[4], bl[4];
            LDSM4(bh, sWhi + boff);
            LDSM4(bl, sWlo + boff);
            MMA(acc[2 * np],     ah, bh);
            MMA(acc[2 * np + 1], ah, bh + 2);
            MMA(acc[2 * np],     ah, bl);
            MMA(acc[2 * np + 1], ah, bl + 2);
            MMA(acc[2 * np],     al, bh);
            MMA(acc[2 * np + 1], al, bh + 2);
        }
    }
}

// ---------------------------------------------------------------------------
// K1: node projections (blockIdx.y: 0 -> psrc (W_s2e), 1 -> ptgt (W_t2e)).
// W converted inline from raw fp32. y==0 CTAs zero their g_agg slice;
// CTA (0,0) publishes the W_e2e image for k_edge.
// ---------------------------------------------------------------------------
__global__ void __launch_bounds__(NT, 2) k_nodeproj(const float* __restrict__ src,
                                                    const float* __restrict__ tgt,
                                                    const float* __restrict__ W_s2e,
                                                    const float* __restrict__ W_t2e,
                                                    const float* __restrict__ W_e2e) {
    extern __shared__ char smem[];
    uint32_t sb = smem_u32(smem);
    int tid = threadIdx.x, wid = tid >> 5, lane = tid & 31;
    const float* X = (blockIdx.y == 0) ? src : tgt;
    const float* Wop = (blockIdx.y == 0) ? W_s2e : W_t2e;
    float* O = (blockIdx.y == 0) ? g_psrc : g_ptgt;
    int r0 = blockIdx.x * TILE;

    if (blockIdx.y == 0) {
        #pragma unroll
        for (int it = 0; it < 4; it++) {
            int i = tid + it * NT;
            int r = i >> 5;
            int c = (i & 31) << 2;
            if (r0 + r < NN)
                *(float4*)(g_agg + (size_t)(r0 + r) * D + c) =
                    make_float4(0.f, 0.f, 0.f, 0.f);
        }
        if (blockIdx.x == 0) {
            unsigned char* hi = g_wimg;
            unsigned char* lo = hi + 32768;
            for (int i = tid; i < D * D; i += NT) {
                int n = i >> 7, k = i & 127;
                float w = W_e2e[i];
                __half h = __float2half_rn(w);
                __half l = __float2half_rn(w - __half2float(h));
                uint32_t off = xswz(n, k);
                *(__half*)(hi + off) = h;
                *(__half*)(lo + off) = l;
            }
        }
    }

    convert_w(Wop, smem + SM_WHI, smem + SM_WLO);
    convert_tile(X, r0, NN, smem + SM_XHI, smem + SM_XLO);
    __syncthreads();
    int m = wid & 3, nw = wid >> 2;
    int mrow = m * 16, ncol = nw * 32;
    float acc[4][4] = {};
    mma_loop(sb + SM_XHI, sb + SM_XLO, sb + SM_WHI, sb + SM_WLO, acc, mrow, ncol, lane);
    __syncthreads();
    int gtid = nw * 32 + lane;
    int gbar = 1 + m;
    float* ostg = (float*)(smem + SM_GSTG);
    #pragma unroll
    for (int h = 0; h < 2; h++) {
        int r = mrow + (lane >> 2) + h * 8;
        #pragma unroll
        for (int nf = 0; nf < 4; nf++) {
            int c = ncol + nf * 8 + (lane & 3) * 2;
            *(float2*)(ostg + r * SSTR + c) = make_float2(acc[nf][h * 2], acc[nf][h * 2 + 1]);
        }
    }
    BAR_GRP(gbar);
    {
        int r = mrow + (gtid >> 3), seg = gtid & 7;
        int n = r0 + r;
        if (n < NN) {
            #pragma unroll
            for (int k = 0; k < 4; k++) {
                int chunk = seg + 8 * k;
                float4 v = *(float4*)(ostg + r * SSTR + chunk * 4);
                *(float4*)(O + (size_t)n * D + chunk * 4) = v;
            }
        }
    }
}

// ---------------------------------------------------------------------------
// K2: fused edge update + aggregation (group-pipelined epilogue; R14 form)
// ---------------------------------------------------------------------------
__global__ void __launch_bounds__(NT, 2) k_edge(
    const float* __restrict__ edge, const int* __restrict__ src_idx,
    const int* __restrict__ tgt_idx, const float* __restrict__ g1,
    const float* __restrict__ b1, float* __restrict__ edge_out) {
    extern __shared__ char smem[];
    uint32_t sb = smem_u32(smem);
    int tid = threadIdx.x, wid = tid >> 5, lane = tid & 31;
    int e0 = blockIdx.x * TILE;
    copy_wimg_async(sb + SM_WHI);               // W_e2e image
    int2* idx = (int2*)(smem + SM_IDX);
    if (tid < TILE) {
        int e = e0 + tid;
        int ec = e < NE ? e : 0;
        idx[tid] = make_int2(src_idx[ec], tgt_idx[ec]);
    }
    convert_tile(edge, e0, NE, smem + SM_XHI, smem + SM_XLO);
    CP_WAIT();
    __syncthreads();
    int m = wid & 3, nw = wid >> 2;
    int mrow = m * 16, ncol = nw * 32;
    float acc[4][4] = {};
    mma_loop(sb + SM_XHI, sb + SM_XLO, sb + SM_WHI, sb + SM_WLO, acc, mrow, ncol, lane);
    __syncthreads();                            // W dead (all warps done)

    int gtid = nw * 32 + lane;                  // 0..127 within M-group
    int gbar = 1 + m;

    // gather stage (group rows only): coalesced psrc[si]+ptgt[ti], MLP=8
    float* gstg = (float*)(smem + SM_GSTG);
    {
        int r = mrow + (gtid >> 3), seg = gtid & 7;
        int2 ii = idx[r];
        const float4* ps = (const float4*)(g_psrc + (size_t)ii.x * D);
        const float4* pt = (const float4*)(g_ptgt + (size_t)ii.y * D);
        float4 a[4], b[4];
        #pragma unroll
        for (int k = 0; k < 4; k++) a[k] = __ldg(ps + seg + 8 * k);
        #pragma unroll
        for (int k = 0; k < 4; k++) b[k] = __ldg(pt + seg + 8 * k);
        #pragma unroll
        for (int k = 0; k < 4; k++) {
            int chunk = seg + 8 * k;
            *(float4*)(gstg + r * SSTR + chunk * 4) =
                make_float4(a[k].x + b[k].x, a[k].y + b[k].y,
                            a[k].z + b[k].z, a[k].w + b[k].w);
        }
    }
    BAR_GRP(gbar);

    float2* red = (float2*)(smem + SM_RED);     // [64][4]

    // pass 1: add gathered sums + silu (in place) + per-row partial sums
    #pragma unroll
    for (int h = 0; h < 2; h++) {
        int r = mrow + (lane >> 2) + h * 8;
        float sum = 0.f, sq = 0.f;
        #pragma unroll
        for (int nf = 0; nf < 4; nf++) {
            int c = ncol + nf * 8 + (lane & 3) * 2;
            float2 pv = *(const float2*)(gstg + r * SSTR + c);
            float s0 = silu(acc[nf][h * 2]     + pv.x);
            float s1 = silu(acc[nf][h * 2 + 1] + pv.y);
            acc[nf][h * 2]     = s0;
            acc[nf][h * 2 + 1] = s1;
            sum += s0 + s1;
            sq  += s0 * s0 + s1 * s1;
        }
        sum += __shfl_xor_sync(0xffffffffu, sum, 1);
        sq  += __shfl_xor_sync(0xffffffffu, sq,  1);
        sum += __shfl_xor_sync(0xffffffffu, sum, 2);
        sq  += __shfl_xor_sync(0xffffffffu, sq,  2);
        if ((lane & 3) == 0) red[r * 4 + nw] = make_float2(sum, sq);
    }
    BAR_GRP(gbar);

    // pass 2: LN + residual (from hi/lo smem) -> output stage
    float* ostg = (float*)(smem + SM_OSTG);
    #pragma unroll
    for (int h = 0; h < 2; h++) {
        int r = mrow + (lane >> 2) + h * 8;
        float2 pa = red[r * 4 + 0];
        float2 pb = red[r * 4 + 1];
        float2 pc = red[r * 4 + 2];
        float2 pd = red[r * 4 + 3];
        float mean = (pa.x + pb.x + pc.x + pd.x) * (1.f / D);
        float var  = (pa.y + pb.y + pc.y + pd.y) * (1.f / D) - mean * mean;
        float rstd = rsqrtf(var + 1e-5f);
        #pragma unroll
        for (int nf = 0; nf < 4; nf++) {
            int c = ncol + nf * 8 + (lane & 3) * 2;
            uint32_t hoff = xswz(r, c);
            float2 hv = __half22float2(*(const __half2*)(smem + SM_XHI + hoff));
            float2 lv = __half22float2(*(const __half2*)(smem + SM_XLO + hoff));
            float2 gv = *(const float2*)(g1 + c);
            float2 bv = *(const float2*)(b1 + c);
            float o0 = (acc[nf][h * 2]     - mean) * rstd * gv.x + bv.x + (hv.x + lv.x);
            float o1 = (acc[nf][h * 2 + 1] - mean) * rstd * gv.y + bv.y + (hv.y + lv.y);
            *(float2*)(ostg + r * SSTR + c) = make_float2(o0, o1);
        }
    }
    BAR_GRP(gbar);

    // writeout (group rows): streaming STG.128 + red.v4 aggregation
    {
        int r = mrow + (gtid >> 3), seg = gtid & 7;
        int e = e0 + r;
        if (e < NE) {
            int ti = idx[r].y;
            float* eo = edge_out + (size_t)e * D;
            float* ap = g_agg + (size_t)ti * D;
            #pragma unroll
            for (int k = 0; k < 4; k++) {
                int chunk = seg + 8 * k;
                float4 v = *(float4*)(ostg + r * SSTR + chunk * 4);
                __stcs((float4*)(eo + chunk * 4), v);
                asm volatile("red.global.add.v4.f32 [%0], {%1,%2,%3,%4};"
                             :: "l"(ap + chunk * 4), "f"(v.x), "f"(v.y), "f"(v.z), "f"(v.w)
                             : "memory");
            }
        }
    }
}

// ---------------------------------------------------------------------------
// K3: target update (two mma phases; W converted inline from raw fp32)
// ---------------------------------------------------------------------------
__global__ void __launch_bounds__(NT, 2) k_tgt(
    const float* __restrict__ tgt, const float* __restrict__ W_e2t,
    const float* __restrict__ W_t2t, const float* __restrict__ g2,
    const float* __restrict__ b2, float* __restrict__ tgt_out) {
    extern __shared__ char smem[];
    uint32_t sb = smem_u32(smem);
    int tid = threadIdx.x, wid = tid >> 5, lane = tid & 31;
    int r0 = blockIdx.x * TILE;
    int m = wid & 3, nw = wid >> 2;
    int mrow = m * 16, ncol = nw * 32;
    float acc[4][4] = {};

    convert_w(W_e2t, smem + SM_WHI, smem + SM_WLO);
    convert_tile(g_agg, r0, NN, smem + SM_XHI, smem + SM_XLO);
    __syncthreads();
    mma_loop(sb + SM_XHI, sb + SM_XLO, sb + SM_WHI, sb + SM_WLO, acc, mrow, ncol, lane);
    __syncthreads();

    convert_w(W_t2t, smem + SM_WHI, smem + SM_WLO);
    convert_tile(tgt, r0, NN, smem + SM_XHI, smem + SM_XLO);
    __syncthreads();
    mma_loop(sb + SM_XHI, sb + SM_XLO, sb + SM_WHI, sb + SM_WLO, acc, mrow, ncol, lane);
    __syncthreads();                            // W dead; XHI/XLO = tgt tile

    int gtid = nw * 32 + lane;
    int gbar = 1 + m;

    float2* red = (float2*)(smem + SM_RED);
    #pragma unroll
    for (int h = 0; h < 2; h++) {
        int r = mrow + (lane >> 2) + h * 8;
        float sum = 0.f, sq = 0.f;
        #pragma unroll
        for (int nf = 0; nf < 4; nf++) {
            float s0 = silu(acc[nf][h * 2]);
            float s1 = silu(acc[nf][h * 2 + 1]);
            acc[nf][h * 2]     = s0;
            acc[nf][h * 2 + 1] = s1;
            sum += s0 + s1;
            sq  += s0 * s0 + s1 * s1;
        }
        sum += __shfl_xor_sync(0xffffffffu, sum, 1);
        sq  += __shfl_xor_sync(0xffffffffu, sq,  1);
        sum += __shfl_xor_sync(0xffffffffu, sum, 2);
        sq  += __shfl_xor_sync(0xffffffffu, sq,  2);
        if ((lane & 3) == 0) red[r * 4 + nw] = make_float2(sum, sq);
    }
    BAR_GRP(gbar);

    float* ostg = (float*)(smem + SM_GSTG);
    #pragma unroll
    for (int h = 0; h < 2; h++) {
        int r = mrow + (lane >> 2) + h * 8;
        float2 pa = red[r * 4 + 0];
        float2 pb = red[r * 4 + 1];
        float2 pc = red[r * 4 + 2];
        float2 pd = red[r * 4 + 3];
        float mean = (pa.x + pb.x + pc.x + pd.x) * (1.f / D);
        float var  = (pa.y + pb.y + pc.y + pd.y) * (1.f / D) - mean * mean;
        float rstd = rsqrtf(var + 1e-5f);
        #pragma unroll
        for (int nf = 0; nf < 4; nf++) {
            int c = ncol + nf * 8 + (lane & 3) * 2;
            uint32_t hoff = xswz(r, c);
            float2 hv = __half22float2(*(const __half2*)(smem + SM_XHI + hoff));
            float2 lv = __half22float2(*(const __half2*)(smem + SM_XLO + hoff));
            float2 gv = *(const float2*)(g2 + c);
            float2 bv = *(const float2*)(b2 + c);
            float o0 = (acc[nf][h * 2]     - mean) * rstd * gv.x + bv.x + (hv.x + lv.x);
            float o1 = (acc[nf][h * 2 + 1] - mean) * rstd * gv.y + bv.y + (hv.y + lv.y);
            *(float2*)(ostg + r * SSTR + c) = make_float2(o0, o1);
        }
    }
    BAR_GRP(gbar);

    {
        int r = mrow + (gtid >> 3), seg = gtid & 7;
        int n = r0 + r;
        if (n < NN) {
            float* to = tgt_out + (size_t)n * D;
            #pragma unroll
            for (int k = 0; k < 4; k++) {
                int chunk = seg + 8 * k;
                float4 v = *(float4*)(ostg + r * SSTR + chunk * 4);
                __stcs((float4*)(to + chunk * 4), v);
            }
        }
    }
}

// ---------------------------------------------------------------------------
extern "C" void kernel_launch(void* const* d_in, const int* in_sizes, int n_in,
                              void* d_out, int out_size) {
    const float* src     = (const float*)d_in[0];
    const float* tgt     = (const float*)d_in[1];
    const float* edge    = (const float*)d_in[2];
    const int*   src_idx = (const int*)d_in[3];
    const int*   tgt_idx = (const int*)d_in[4];
    const float* W_s2e   = (const float*)d_in[5];
    const float* W_t2e   = (const float*)d_in[6];
    const float* W_e2e   = (const float*)d_in[7];
    const float* W_e2t   = (const float*)d_in[8];
    const float* W_t2t   = (const float*)d_in[9];
    const float* ln1_g   = (const float*)d_in[10];
    const float* ln1_b   = (const float*)d_in[11];
    const float* ln2_g   = (const float*)d_in[12];
    const float* ln2_b   = (const float*)d_in[13];

    float* edge_out = (float*)d_out;
    float* tgt_out  = edge_out + (size_t)NE * D;

    cudaFuncSetAttribute(k_nodeproj, cudaFuncAttributeMaxDynamicSharedMemorySize, SM_TOTAL);
    cudaFuncSetAttribute(k_edge,     cudaFuncAttributeMaxDynamicSharedMemorySize, SM_TOTAL);
    cudaFuncSetAttribute(k_tgt,      cudaFuncAttributeMaxDynamicSharedMemorySize, SM_TOTAL);

    dim3 gn((NN + TILE - 1) / TILE, 2);
    k_nodeproj<<<gn, NT, SM_TOTAL>>>(src, tgt, W_s2e, W_t2e, W_e2e);
    k_edge<<<(NE + TILE - 1) / TILE, NT, SM_TOTAL>>>(edge, src_idx, tgt_idx,
                                                     ln1_g, ln1_b, edge_out);
    k_tgt<<<(NN + TILE - 1) / TILE, NT, SM_TOTAL>>>(tgt, W_e2t, W_t2t,
                                                    ln2_g, ln2_b, tgt_out);
}

// round 17
// speedup vs baseline: 1.0389x; 1.0389x over previous
#include <cuda_runtime.h>
#include <cuda_fp16.h>
#include <cstdint>

#define D 128
#define NN 50000
#define NE 500000
#define TILE 64                     // X-tile rows per CTA
#define NT 512                      // 16 warps: 4(M) x 4(N)
#define SSTR 136                    // stage row stride in floats (136%32==8)

#define BAR_GRP(id) asm volatile("bar.sync %0, 128;" :: "r"(id) : "memory")

// ---------------- scratch (__device__ globals) ------------------------------
__device__ float g_psrc[(size_t)NN * D];
__device__ float g_ptgt[(size_t)NN * D];
__device__ float g_agg [(size_t)NN * D];
__device__ unsigned char g_wimg[3 * 65536];   // [W_e2e, W_e2t, W_t2t][hi|lo] swizzled

// ---------------- smem layout (~105KB -> 2 CTAs/SM) -------------------------
#define SM_XHI  0                   // 16KB (alive through epilogue: residual)
#define SM_XLO  16384               // 16KB
#define SM_WHI  32768               // 32KB (dead after mma)
#define SM_WLO  65536               // 32KB (dead after mma)
#define SM_GSTG 32768               // gather stage (aliases W, post-mma only)
#define SM_OSTG 67584               // output stage (post-mma only)
#define SM_RED  102400              // float2 red[64][4] = 2KB
#define SM_IDX  104448              // int2 idx[64] = 512B
#define SM_TOTAL 104960

// swizzled fp16 tile: row r x col c; 256B/row, 16B chunks; chunk ^= (r&7)
__device__ __forceinline__ uint32_t xswz(int r, int c) {
    return (uint32_t)(r * 256 + (((c >> 3) ^ (r & 7)) << 4) + (c & 7) * 2);
}

#define LDSM4(r, a) \
    asm volatile("ldmatrix.sync.aligned.m8n8.x4.shared.b16 {%0,%1,%2,%3}, [%4];" \
        : "=r"((r)[0]), "=r"((r)[1]), "=r"((r)[2]), "=r"((r)[3]) : "r"(a))
#define MMA(c, a, b) \
    asm volatile("mma.sync.aligned.m16n8k16.row.col.f32.f16.f16.f32 " \
        "{%0,%1,%2,%3}, {%4,%5,%6,%7}, {%8,%9}, {%0,%1,%2,%3};" \
        : "+f"((c)[0]), "+f"((c)[1]), "+f"((c)[2]), "+f"((c)[3]) \
        : "r"((a)[0]), "r"((a)[1]), "r"((a)[2]), "r"((a)[3]), "r"((b)[0]), "r"((b)[1]))
#define CP16(dst, src) \
    asm volatile("cp.async.cg.shared.global [%0], [%1], 16;" :: "r"(dst), "l"(src))
#define CP_COMMIT() asm volatile("cp.async.commit_group;" ::: "memory")
#define CP_WAIT()   asm volatile("cp.async.wait_group 0;" ::: "memory")
#define PF_L2(p)    asm volatile("prefetch.global.L2 [%0];" :: "l"(p))

__device__ __forceinline__ uint32_t smem_u32(const void* p) {
    uint32_t a;
    asm("{ .reg .u64 t; cvta.to.shared.u64 t, %1; cvt.u32.u64 %0, t; }" : "=r"(a) : "l"(p));
    return a;
}
__device__ __forceinline__ unsigned short h_us(__half h) { return __half_as_ushort(h); }
__device__ __forceinline__ float silu(float m) { return m * (1.f / (1.f + __expf(-m))); }

// convert fp32 tile [TILE x 128] -> split hi/lo fp16 in swizzled smem (stream loads)
__device__ __forceinline__ void convert_tile(const float* __restrict__ src, int row0,
                                             int nrows, char* a_hi, char* a_lo) {
    #pragma unroll
    for (int it = 0; it < 4; it++) {
        int i = threadIdx.x + it * NT;
        int r = i >> 5;
        int c = (i & 31) << 2;
        float4 v = make_float4(0.f, 0.f, 0.f, 0.f);
        if (row0 + r < nrows) v = __ldcs((const float4*)(src + (size_t)(row0 + r) * D + c));
        __half h0 = __float2half_rn(v.x), h1 = __float2half_rn(v.y);
        __half h2 = __float2half_rn(v.z), h3 = __float2half_rn(v.w);
        __half l0 = __float2half_rn(v.x - __half2float(h0));
        __half l1 = __float2half_rn(v.y - __half2float(h1));
        __half l2 = __float2half_rn(v.z - __half2float(h2));
        __half l3 = __float2half_rn(v.w - __half2float(h3));
        uint32_t off = xswz(r, c);
        *(uint2*)(a_hi + off) = make_uint2((uint32_t)h_us(h0) | ((uint32_t)h_us(h1) << 16),
                                           (uint32_t)h_us(h2) | ((uint32_t)h_us(h3) << 16));
        *(uint2*)(a_lo + off) = make_uint2((uint32_t)h_us(l0) | ((uint32_t)h_us(l1) << 16),
                                           (uint32_t)h_us(l2) | ((uint32_t)h_us(l3) << 16));
    }
}

// convert raw fp32 W [128 x 128] -> split hi/lo fp16 in swizzled smem
__device__ __forceinline__ void convert_w(const float* __restrict__ W,
                                          char* w_hi, char* w_lo) {
    #pragma unroll
    for (int it = 0; it < 8; it++) {
        int i = threadIdx.x + it * NT;       // 4096 float4 slots
        int r = i >> 5;
        int c = (i & 31) << 2;
        float4 v = *(const float4*)(W + (size_t)r * D + c);
        __half h0 = __float2half_rn(v.x), h1 = __float2half_rn(v.y);
        __half h2 = __float2half_rn(v.z), h3 = __float2half_rn(v.w);
        __half l0 = __float2half_rn(v.x - __half2float(h0));
        __half l1 = __float2half_rn(v.y - __half2float(h1));
        __half l2 = __float2half_rn(v.z - __half2float(h2));
        __half l3 = __float2half_rn(v.w - __half2float(h3));
        uint32_t off = xswz(r, c);
        *(uint2*)(w_hi + off) = make_uint2((uint32_t)h_us(h0) | ((uint32_t)h_us(h1) << 16),
                                           (uint32_t)h_us(h2) | ((uint32_t)h_us(h3) << 16));
        *(uint2*)(w_lo + off) = make_uint2((uint32_t)h_us(l0) | ((uint32_t)h_us(l1) << 16),
                                           (uint32_t)h_us(l2) | ((uint32_t)h_us(l3) << 16));
    }
}

__device__ __forceinline__ void copy_wimg_async(uint32_t sdst, int widx) {
    const char* src = (const char*)g_wimg + (size_t)widx * 65536;
    #pragma unroll 2
    for (int i = threadIdx.x; i < 4096; i += NT)
        CP16(sdst + i * 16, src + i * 16);
    CP_COMMIT();
}

// ---------------------------------------------------------------------------
// GEMM mainloop: 16 warps 4(M)x4(N); warp tile 16x32; acc[4][4] f32.
// 3-term split: HH + HL + LH.
// ---------------------------------------------------------------------------
__device__ __forceinline__ void mma_loop(uint32_t sXhi, uint32_t sXlo,
                                         uint32_t sWhi, uint32_t sWlo,
                                         float (&acc)[4][4], int mrow, int ncol, int lane) {
    int arow = mrow + (lane & 15);
    int g = lane >> 3;
    int brow = ncol + ((g >> 1) << 3) + (lane & 7);
    int bkc = g & 1;
    #pragma unroll
    for (int ks = 0; ks < 8; ks++) {
        int ac16 = ks * 2 + (lane >> 4);
        uint32_t aoff = (uint32_t)(arow * 256 + ((ac16 ^ (arow & 7)) << 4));
        uint32_t ah[4], al[4];
        LDSM4(ah, sXhi + aoff);
        LDSM4(al, sXlo + aoff);
        int bc16 = ks * 2 + bkc;
        #pragma unroll
        for (int np = 0; np < 2; np++) {
            int n = brow + np * 16;
            uint32_t boff = (uint32_t)(n * 256 + ((bc16 ^ (n & 7)) << 4));
            uint32_t bh[4], bl[4];
            LDSM4(bh, sWhi + boff);
            LDSM4(bl, sWlo + boff);
            MMA(acc[2 * np],     ah, bh);
            MMA(acc[2 * np + 1], ah, bh + 2);
            MMA(acc[2 * np],     ah, bl);
            MMA(acc[2 * np + 1], ah, bl + 2);
            MMA(acc[2 * np],     al, bh);
            MMA(acc[2 * np + 1], al, bh + 2);
        }
    }
}

// ---------------------------------------------------------------------------
// K1: node projections (blockIdx.y: 0 -> psrc (W_s2e), 1 -> ptgt (W_t2e)).
// W converted inline from raw fp32. y==0 CTAs zero their g_agg slice;
// y==0 CTAs 0..2 publish g_wimg[0..2] (= W_e2e, W_e2t, W_t2t).
// ---------------------------------------------------------------------------
__global__ void __launch_bounds__(NT, 2) k_nodeproj(const float* __restrict__ src,
                                                    const float* __restrict__ tgt,
                                                    const float* __restrict__ W_s2e,
                                                    const float* __restrict__ W_t2e,
                                                    const float* __restrict__ W_e2e,
                                                    const float* __restrict__ W_e2t,
                                                    const float* __restrict__ W_t2t) {
    extern __shared__ char smem[];
    uint32_t sb = smem_u32(smem);
    int tid = threadIdx.x, wid = tid >> 5, lane = tid & 31;
    const float* X = (blockIdx.y == 0) ? src : tgt;
    const float* Wop = (blockIdx.y == 0) ? W_s2e : W_t2e;
    float* O = (blockIdx.y == 0) ? g_psrc : g_ptgt;
    int r0 = blockIdx.x * TILE;

    if (blockIdx.y == 0) {
        #pragma unroll
        for (int it = 0; it < 4; it++) {
            int i = tid + it * NT;
            int r = i >> 5;
            int c = (i & 31) << 2;
            if (r0 + r < NN)
                *(float4*)(g_agg + (size_t)(r0 + r) * D + c) =
                    make_float4(0.f, 0.f, 0.f, 0.f);
        }
        if (blockIdx.x < 3) {
            const float* Wp = (blockIdx.x == 0) ? W_e2e : (blockIdx.x == 1) ? W_e2t : W_t2t;
            unsigned char* hi = g_wimg + (size_t)blockIdx.x * 65536;
            unsigned char* lo = hi + 32768;
            for (int i = tid; i < D * D; i += NT) {
                int n = i >> 7, k = i & 127;
                float w = Wp[i];
                __half h = __float2half_rn(w);
                __half l = __float2half_rn(w - __half2float(h));
                uint32_t off = xswz(n, k);
                *(__half*)(hi + off) = h;
                *(__half*)(lo + off) = l;
            }
        }
    }

    convert_w(Wop, smem + SM_WHI, smem + SM_WLO);
    convert_tile(X, r0, NN, smem + SM_XHI, smem + SM_XLO);
    __syncthreads();
    int m = wid & 3, nw = wid >> 2;
    int mrow = m * 16, ncol = nw * 32;
    float acc[4][4] = {};
    mma_loop(sb + SM_XHI, sb + SM_XLO, sb + SM_WHI, sb + SM_WLO, acc, mrow, ncol, lane);
    __syncthreads();
    int gtid = nw * 32 + lane;
    int gbar = 1 + m;
    float* ostg = (float*)(smem + SM_GSTG);
    #pragma unroll
    for (int h = 0; h < 2; h++) {
        int r = mrow + (lane >> 2) + h * 8;
        #pragma unroll
        for (int nf = 0; nf < 4; nf++) {
            int c = ncol + nf * 8 + (lane & 3) * 2;
            *(float2*)(ostg + r * SSTR + c) = make_float2(acc[nf][h * 2], acc[nf][h * 2 + 1]);
        }
    }
    BAR_GRP(gbar);
    {
        int r = mrow + (gtid >> 3), seg = gtid & 7;
        int n = r0 + r;
        if (n < NN) {
            #pragma unroll
            for (int k = 0; k < 4; k++) {
                int chunk = seg + 8 * k;
                float4 v = *(float4*)(ostg + r * SSTR + chunk * 4);
                *(float4*)(O + (size_t)n * D + chunk * 4) = v;
            }
        }
    }
}

// ---------------------------------------------------------------------------
// K2: fused edge update + aggregation.
// NEW: L2-prefetch of psrc/ptgt gather rows issued BEFORE the mma, so the
// post-mma gathers hit L2 instead of DRAM.
// ---------------------------------------------------------------------------
__global__ void __launch_bounds__(NT, 2) k_edge(
    const float* __restrict__ edge, const int* __restrict__ src_idx,
    const int* __restrict__ tgt_idx, const float* __restrict__ g1,
    const float* __restrict__ b1, float* __restrict__ edge_out) {
    extern __shared__ char smem[];
    uint32_t sb = smem_u32(smem);
    int tid = threadIdx.x, wid = tid >> 5, lane = tid & 31;
    int e0 = blockIdx.x * TILE;
    copy_wimg_async(sb + SM_WHI, 0);            // W_e2e image
    int2* idx = (int2*)(smem + SM_IDX);
    if (tid < TILE) {
        int e = e0 + tid;
        int ec = e < NE ? e : 0;
        int si = src_idx[ec];
        int ti = tgt_idx[ec];
        idx[tid] = make_int2(si, ti);
        // warm L2 with this row's gather targets (4 x 128B lines each)
        const char* ps = (const char*)(g_psrc + (size_t)si * D);
        const char* pt = (const char*)(g_ptgt + (size_t)ti * D);
        #pragma unroll
        for (int k = 0; k < 4; k++) {
            PF_L2(ps + k * 128);
            PF_L2(pt + k * 128);
        }
    }
    convert_tile(edge, e0, NE, smem + SM_XHI, smem + SM_XLO);
    CP_WAIT();
    __syncthreads();
    int m = wid & 3, nw = wid >> 2;
    int mrow = m * 16, ncol = nw * 32;
    float acc[4][4] = {};
    mma_loop(sb + SM_XHI, sb + SM_XLO, sb + SM_WHI, sb + SM_WLO, acc, mrow, ncol, lane);
    __syncthreads();                            // W dead (all warps done)

    int gtid = nw * 32 + lane;                  // 0..127 within M-group
    int gbar = 1 + m;

    // gather stage (group rows only): coalesced psrc[si]+ptgt[ti], MLP=8
    float* gstg = (float*)(smem + SM_GSTG);
    {
        int r = mrow + (gtid >> 3), seg = gtid & 7;
        int2 ii = idx[r];
        const float4* ps = (const float4*)(g_psrc + (size_t)ii.x * D);
        const float4* pt = (const float4*)(g_ptgt + (size_t)ii.y * D);
        float4 a[4], b[4];
        #pragma unroll
        for (int k = 0; k < 4; k++) a[k] = __ldg(ps + seg + 8 * k);
        #pragma unroll
        for (int k = 0; k < 4; k++) b[k] = __ldg(pt + seg + 8 * k);
        #pragma unroll
        for (int k = 0; k < 4; k++) {
            int chunk = seg + 8 * k;
            *(float4*)(gstg + r * SSTR + chunk * 4) =
                make_float4(a[k].x + b[k].x, a[k].y + b[k].y,
                            a[k].z + b[k].z, a[k].w + b[k].w);
        }
    }
    BAR_GRP(gbar);

    float2* red = (float2*)(smem + SM_RED);     // [64][4]

    // pass 1: add gathered sums + silu (in place) + per-row partial sums
    #pragma unroll
    for (int h = 0; h < 2; h++) {
        int r = mrow + (lane >> 2) + h * 8;
        float sum = 0.f, sq = 0.f;
        #pragma unroll
        for (int nf = 0; nf < 4; nf++) {
            int c = ncol + nf * 8 + (lane & 3) * 2;
            float2 pv = *(const float2*)(gstg + r * SSTR + c);
            float s0 = silu(acc[nf][h * 2]     + pv.x);
            float s1 = silu(acc[nf][h * 2 + 1] + pv.y);
            acc[nf][h * 2]     = s0;
            acc[nf][h * 2 + 1] = s1;
            sum += s0 + s1;
            sq  += s0 * s0 + s1 * s1;
        }
        sum += __shfl_xor_sync(0xffffffffu, sum, 1);
        sq  += __shfl_xor_sync(0xffffffffu, sq,  1);
        sum += __shfl_xor_sync(0xffffffffu, sum, 2);
        sq  += __shfl_xor_sync(0xffffffffu, sq,  2);
        if ((lane & 3) == 0) red[r * 4 + nw] = make_float2(sum, sq);
    }
    BAR_GRP(gbar);

    // pass 2: LN + residual (from hi/lo smem) -> output stage
    float* ostg = (float*)(smem + SM_OSTG);
    #pragma unroll
    for (int h = 0; h < 2; h++) {
        int r = mrow + (lane >> 2) + h * 8;
        float2 pa = red[r * 4 + 0];
        float2 pb = red[r * 4 + 1];
        float2 pc = red[r * 4 + 2];
        float2 pd = red[r * 4 + 3];
        float mean = (pa.x + pb.x + pc.x + pd.x) * (1.f / D);
        float var  = (pa.y + pb.y + pc.y + pd.y) * (1.f / D) - mean * mean;
        float rstd = rsqrtf(var + 1e-5f);
        #pragma unroll
        for (int nf = 0; nf < 4; nf++) {
            int c = ncol + nf * 8 + (lane & 3) * 2;
            uint32_t hoff = xswz(r, c);
            float2 hv = __half22float2(*(const __half2*)(smem + SM_XHI + hoff));
            float2 lv = __half22float2(*(const __half2*)(smem + SM_XLO + hoff));
            float2 gv = *(const float2*)(g1 + c);
            float2 bv = *(const float2*)(b1 + c);
            float o0 = (acc[nf][h * 2]     - mean) * rstd * gv.x + bv.x + (hv.x + lv.x);
            float o1 = (acc[nf][h * 2 + 1] - mean) * rstd * gv.y + bv.y + (hv.y + lv.y);
            *(float2*)(ostg + r * SSTR + c) = make_float2(o0, o1);
        }
    }
    BAR_GRP(gbar);

    // writeout (group rows): streaming STG.128 + red.v4 aggregation
    {
        int r = mrow + (gtid >> 3), seg = gtid & 7;
        int e = e0 + r;
        if (e < NE) {
            int ti = idx[r].y;
            float* eo = edge_out + (size_t)e * D;
            float* ap = g_agg + (size_t)ti * D;
            #pragma unroll
            for (int k = 0; k < 4; k++) {
                int chunk = seg + 8 * k;
                float4 v = *(float4*)(ostg + r * SSTR + chunk * 4);
                __stcs((float4*)(eo + chunk * 4), v);
                asm volatile("red.global.add.v4.f32 [%0], {%1,%2,%3,%4};"
                             :: "l"(ap + chunk * 4), "f"(v.x), "f"(v.y), "f"(v.z), "f"(v.w)
                             : "memory");
            }
        }
    }
}

// ---------------------------------------------------------------------------
// K3: target update (two mma phases; image-copied W — R14 form)
// ---------------------------------------------------------------------------
__global__ void __launch_bounds__(NT, 2) k_tgt(
    const float* __restrict__ tgt, const float* __restrict__ g2,
    const float* __restrict__ b2, float* __restrict__ tgt_out) {
    extern __shared__ char smem[];
    uint32_t sb = smem_u32(smem);
    int tid = threadIdx.x, wid = tid >> 5, lane = tid & 31;
    int r0 = blockIdx.x * TILE;
    int m = wid & 3, nw = wid >> 2;
    int mrow = m * 16, ncol = nw * 32;
    float acc[4][4] = {};

    copy_wimg_async(sb + SM_WHI, 1);            // W_e2t image
    convert_tile(g_agg, r0, NN, smem + SM_XHI, smem + SM_XLO);
    CP_WAIT();
    __syncthreads();
    mma_loop(sb + SM_XHI, sb + SM_XLO, sb + SM_WHI, sb + SM_WLO, acc, mrow, ncol, lane);
    __syncthreads();

    copy_wimg_async(sb + SM_WHI, 2);            // W_t2t image
    convert_tile(tgt, r0, NN, smem + SM_XHI, smem + SM_XLO);
    CP_WAIT();
    __syncthreads();
    mma_loop(sb + SM_XHI, sb + SM_XLO, sb + SM_WHI, sb + SM_WLO, acc, mrow, ncol, lane);
    __syncthreads();                            // W dead; XHI/XLO = tgt tile

    int gtid = nw * 32 + lane;
    int gbar = 1 + m;

    float2* red = (float2*)(smem + SM_RED);
    #pragma unroll
    for (int h = 0; h < 2; h++) {
        int r = mrow + (lane >> 2) + h * 8;
        float sum = 0.f, sq = 0.f;
        #pragma unroll
        for (int nf = 0; nf < 4; nf++) {
            float s0 = silu(acc[nf][h * 2]);
            float s1 = silu(acc[nf][h * 2 + 1]);
            acc[nf][h * 2]     = s0;
            acc[nf][h * 2 + 1] = s1;
            sum += s0 + s1;
            sq  += s0 * s0 + s1 * s1;
        }
        sum += __shfl_xor_sync(0xffffffffu, sum, 1);
        sq  += __shfl_xor_sync(0xffffffffu, sq,  1);
        sum += __shfl_xor_sync(0xffffffffu, sum, 2);
        sq  += __shfl_xor_sync(0xffffffffu, sq,  2);
        if ((lane & 3) == 0) red[r * 4 + nw] = make_float2(sum, sq);
    }
    BAR_GRP(gbar);

    float* ostg = (float*)(smem + SM_OSTG);
    #pragma unroll
    for (int h = 0; h < 2; h++) {
        int r = mrow + (lane >> 2) + h * 8;
        float2 pa = red[r * 4 + 0];
        float2 pb = red[r * 4 + 1];
        float2 pc = red[r * 4 + 2];
        float2 pd = red[r * 4 + 3];
        float mean = (pa.x + pb.x + pc.x + pd.x) * (1.f / D);
        float var  = (pa.y + pb.y + pc.y + pd.y) * (1.f / D) - mean * mean;
        float rstd = rsqrtf(var + 1e-5f);
        #pragma unroll
        for (int nf = 0; nf < 4; nf++) {
            int c = ncol + nf * 8 + (lane & 3) * 2;
            uint32_t hoff = xswz(r, c);
            float2 hv = __half22float2(*(const __half2*)(smem + SM_XHI + hoff));
            float2 lv = __half22float2(*(const __half2*)(smem + SM_XLO + hoff));
            float2 gv = *(const float2*)(g2 + c);
            float2 bv = *(const float2*)(b2 + c);
            float o0 = (acc[nf][h * 2]     - mean) * rstd * gv.x + bv.x + (hv.x + lv.x);
            float o1 = (acc[nf][h * 2 + 1] - mean) * rstd * gv.y + bv.y + (hv.y + lv.y);
            *(float2*)(ostg + r * SSTR + c) = make_float2(o0, o1);
        }
    }
    BAR_GRP(gbar);

    {
        int r = mrow + (gtid >> 3), seg = gtid & 7;
        int n = r0 + r;
        if (n < NN) {
            float* to = tgt_out + (size_t)n * D;
            #pragma unroll
            for (int k = 0; k < 4; k++) {
                int chunk = seg + 8 * k;
                float4 v = *(float4*)(ostg + r * SSTR + chunk * 4);
                __stcs((float4*)(to + chunk * 4), v);
            }
        }
    }
}

// ---------------------------------------------------------------------------
extern "C" void kernel_launch(void* const* d_in, const int* in_sizes, int n_in,
                              void* d_out, int out_size) {
    const float* src     = (const float*)d_in[0];
    const float* tgt     = (const float*)d_in[1];
    const float* edge    = (const float*)d_in[2];
    const int*   src_idx = (const int*)d_in[3];
    const int*   tgt_idx = (const int*)d_in[4];
    const float* W_s2e   = (const float*)d_in[5];
    const float* W_t2e   = (const float*)d_in[6];
    const float* W_e2e   = (const float*)d_in[7];
    const float* W_e2t   = (const float*)d_in[8];
    const float* W_t2t   = (const float*)d_in[9];
    const float* ln1_g   = (const float*)d_in[10];
    const float* ln1_b   = (const float*)d_in[11];
    const float* ln2_g   = (const float*)d_in[12];
    const float* ln2_b   = (const float*)d_in[13];

    float* edge_out = (float*)d_out;
    float* tgt_out  = edge_out + (size_t)NE * D;

    cudaFuncSetAttribute(k_nodeproj, cudaFuncAttributeMaxDynamicSharedMemorySize, SM_TOTAL);
    cudaFuncSetAttribute(k_edge,     cudaFuncAttributeMaxDynamicSharedMemorySize, SM_TOTAL);
    cudaFuncSetAttribute(k_tgt,      cudaFuncAttributeMaxDynamicSharedMemorySize, SM_TOTAL);

    dim3 gn((NN + TILE - 1) / TILE, 2);
    k_nodeproj<<<gn, NT, SM_TOTAL>>>(src, tgt, W_s2e, W_t2e, W_e2e, W_e2t, W_t2t);
    k_edge<<<(NE + TILE - 1) / TILE, NT, SM_TOTAL>>>(edge, src_idx, tgt_idx,
                                                     ln1_g, ln1_b, edge_out);
    k_tgt<<<(NN + TILE - 1) / TILE, NT, SM_TOTAL>>>(tgt, ln2_g, ln2_b, tgt_out);
}